// round 14
// baseline (speedup 1.0000x reference)
#include <cuda_runtime.h>

typedef unsigned long long u64t;

// ---- packed f32x2 helpers (sm_103a) ----
__device__ __forceinline__ u64t pack2(float x, float y){
    u64t r; asm("mov.b64 %0,{%1,%2};" : "=l"(r) : "f"(x), "f"(y)); return r;
}
__device__ __forceinline__ u64t pack2d(float x){
    u64t r; asm("mov.b64 %0,{%1,%1};" : "=l"(r) : "f"(x)); return r;
}
__device__ __forceinline__ float2 unpack2(u64t a){
    float2 r; asm("mov.b64 {%0,%1},%2;" : "=f"(r.x), "=f"(r.y) : "l"(a)); return r;
}
__device__ __forceinline__ u64t fma2_(u64t a, u64t b, u64t c){
    u64t d; asm("fma.rn.f32x2 %0,%1,%2,%3;" : "=l"(d) : "l"(a), "l"(b), "l"(c)); return d;
}
__device__ __forceinline__ u64t mul2_(u64t a, u64t b){
    u64t d; asm("mul.rn.f32x2 %0,%1,%2;" : "=l"(d) : "l"(a), "l"(b)); return d;
}
__device__ __forceinline__ u64t add2_(u64t a, u64t b){
    u64t d; asm("add.rn.f32x2 %0,%1,%2;" : "=l"(d) : "l"(a), "l"(b)); return d;
}

#define NB     32                 // batches
#define NI     4096               // input capsules
#define NO     32                 // output capsules
#define NPAIR  (NI / 2)           // 2048 capsule pairs
#define CI     32                 // i per chunk
#define CP     (CI / 2)           // 16 pairs per chunk
#define NCHUNK (NI / CI)          // 128
#define EL     (NB * NO * 16)     // 16384 output elements
#define PSLAB  EL                 // floats per partial slab

// scratch (static device globals — no allocations)
__device__ __align__(16) u64t  g_wt2[NPAIR * 16 * NO];   // W i-paired: [IP][k][o], 8 MB
__device__ __align__(16) u64t  g_pp [NB * NPAIR * 16];   // poses i-paired: [b][IP][k], 8 MB
__device__ __align__(16) float g_part[NCHUNK * PSLAB];   // 8 MB partials: [chunk][b][o][16]
__device__ __align__(16) float g_v[EL];                  // v for logits this pass
__device__ __align__(16) float g_vsum[EL];               // running sum of v's

// ---------------------------------------------------------------------------
// Prep (one launch): blocks [0,4096) build g_wt2, blocks [4096,8192) build g_pp.
// g_wt2[(IP*16+k)*32+o] = pack(w[o][2IP][k], w[o][2IP+1][k]),  k = y*4+z
// g_pp [(b*NPAIR+IP)*16+k] = pack(P[b][2IP][k], P[b][2IP+1][k]), k = x*4+y
// ---------------------------------------------------------------------------
__global__ __launch_bounds__(256) void prep_kernel(const float* __restrict__ poses,
                                                   const float* __restrict__ w)
{
    int bid = blockIdx.x;
    int tid = threadIdx.x;
    if (bid < 4096) {
        int idx = bid * 256 + tid;                // (IP*16 + k)*32 + o
        int o  = idx & 31;
        int k  = (idx >> 5) & 15;
        int ip = idx >> 9;
        const float* s0 = w + ((size_t)o * NI + 2 * ip) * 16 + k;
        g_wt2[idx] = pack2(__ldg(s0), __ldg(s0 + 16));
    } else {
        int idx = (bid - 4096) * 256 + tid;       // (b*NPAIR + IP)*16 + k
        int k  = idx & 15;
        int ip = (idx >> 4) & (NPAIR - 1);
        int b  = idx >> 15;
        const float* s0 = poses + ((size_t)b * NI + 2 * ip) * 16 + k;
        g_pp[idx] = pack2(__ldg(s0), __ldg(s0 + 16));
    }
}

// ---------------------------------------------------------------------------
// pass1: warp owns (chunk c, batches b0 and b0+1): lane = o, loops CP pairs.
// Each Wk load is reused for TWO batches -> W L1 traffic halved, 2x FMA per
// load. sacc per batch in regs (~108 total, no spills at 128 cap).
// ---------------------------------------------------------------------------
__global__ __launch_bounds__(128, 4) void pass1_kernel()
{
    __shared__ __align__(16) u64t Ps[4][2][CP * 16];   // 16 KB
    const int lane = threadIdx.x & 31;
    const int warp = threadIdx.x >> 5;
    const int c    = blockIdx.x;
    const int b0   = (blockIdx.y * 4 + warp) * 2;
    const int o    = lane;

    // stage paired poses for both batches
    {
        const u64t* s0 = g_pp + ((size_t)b0       * NPAIR + (size_t)c * CP) * 16;
        const u64t* s1 = g_pp + ((size_t)(b0 + 1) * NPAIR + (size_t)c * CP) * 16;
        #pragma unroll
        for (int j = 0; j < 8; j++) {
            Ps[warp][0][lane + 32 * j] = __ldg(s0 + lane + 32 * j);
            Ps[warp][1][lane + 32 * j] = __ldg(s1 + lane + 32 * j);
        }
    }
    __syncwarp();

    u64t sacc0[16], sacc1[16];
    #pragma unroll
    for (int k = 0; k < 16; k++) { sacc0[k] = 0ull; sacc1[k] = 0ull; }

    const u64t* Wb = (const u64t*)g_wt2 + (size_t)c * CP * 16 * 32 + o;

    #pragma unroll 1
    for (int ip = 0; ip < CP; ip++) {
        u64t Wk[16];
        #pragma unroll
        for (int k = 0; k < 16; k++) Wk[k] = __ldg(Wb + (ip * 16 + k) * 32);

        const u64t* P0 = &Ps[warp][0][ip * 16];
        const u64t* P1 = &Ps[warp][1][ip * 16];

        #pragma unroll
        for (int y = 0; y < 4; y++)
            #pragma unroll
            for (int x = 0; x < 4; x++) {
                u64t p0 = P0[x * 4 + y];
                u64t p1 = P1[x * 4 + y];
                #pragma unroll
                for (int z = 0; z < 4; z++) {
                    sacc0[x * 4 + z] = fma2_(p0, Wk[y * 4 + z], sacc0[x * 4 + z]);
                    sacc1[x * 4 + z] = fma2_(p1, Wk[y * 4 + z], sacc1[x * 4 + z]);
                }
            }
    }

    // writeout both batches: fold (i0,i1) halves
    #pragma unroll
    for (int bb = 0; bb < 2; bb++) {
        u64t* sa = bb ? sacc1 : sacc0;
        float4* gp = (float4*)(g_part + (((size_t)c * NB + (b0 + bb)) * NO + o) * 16);
        #pragma unroll
        for (int x = 0; x < 4; x++) {
            float2 a0 = unpack2(sa[x * 4 + 0]);
            float2 a1 = unpack2(sa[x * 4 + 1]);
            float2 a2 = unpack2(sa[x * 4 + 2]);
            float2 a3 = unpack2(sa[x * 4 + 3]);
            gp[x] = make_float4(a0.x + a0.y, a1.x + a1.y, a2.x + a2.y, a3.x + a3.y);
        }
    }
}

// ---------------------------------------------------------------------------
// pass2/3 (R9 body): warp owns (batch b, chunk c); lane = o; vd in smem.
// ---------------------------------------------------------------------------
__device__ __forceinline__ void pass23_body(int c, int b, int lane,
                                            u64t* PsW, u64t* VdW)
{
    const int o = lane;

    {
        const u64t* src = g_pp + ((size_t)b * NPAIR + (size_t)c * CP) * 16;
        #pragma unroll
        for (int j = 0; j < 8; j++) PsW[lane + 32 * j] = __ldg(src + lane + 32 * j);
    }
    {
        const float4* gv4 = (const float4*)(g_v + ((size_t)b * NO + o) * 16);
        #pragma unroll
        for (int q = 0; q < 4; q++) {
            float4 a = __ldg(gv4 + q);
            VdW[(4 * q + 0) * 32 + o] = pack2d(a.x);
            VdW[(4 * q + 1) * 32 + o] = pack2d(a.y);
            VdW[(4 * q + 2) * 32 + o] = pack2d(a.z);
            VdW[(4 * q + 3) * 32 + o] = pack2d(a.w);
        }
    }
    __syncwarp();

    u64t sacc[16];
    #pragma unroll
    for (int k = 0; k < 16; k++) sacc[k] = 0ull;

    const u64t* Wb = (const u64t*)g_wt2 + (size_t)c * CP * 16 * 32 + o;

    #pragma unroll 1
    for (int ip = 0; ip < CP; ip++) {
        u64t Wk[16];
        #pragma unroll
        for (int k = 0; k < 16; k++) Wk[k] = __ldg(Wb + (ip * 16 + k) * 32);

        const u64t* Pp = PsW + ip * 16;

        // votes V[x*4+z] halves = (V_i0, V_i1)
        u64t V[16];
        #pragma unroll
        for (int x = 0; x < 4; x++) {
            u64t p0 = Pp[x * 4];
            #pragma unroll
            for (int z = 0; z < 4; z++) V[x * 4 + z] = mul2_(p0, Wk[z]);
        }
        #pragma unroll
        for (int y = 1; y < 4; y++)
            #pragma unroll
            for (int x = 0; x < 4; x++) {
                u64t p = Pp[x * 4 + y];
                #pragma unroll
                for (int z = 0; z < 4; z++)
                    V[x * 4 + z] = fma2_(p, Wk[y * 4 + z], V[x * 4 + z]);
            }

        // both logits in one packed dot; vd (duplicated) streamed from shared
        u64t da = mul2_(V[0], VdW[0 * 32 + o]);
        u64t db = mul2_(V[1], VdW[1 * 32 + o]);
        #pragma unroll
        for (int k = 2; k < 16; k += 2) {
            da = fma2_(V[k],     VdW[k * 32 + o],       da);
            db = fma2_(V[k + 1], VdW[(k + 1) * 32 + o], db);
        }
        float2 dl = unpack2(add2_(da, db));

        float e0 = __expf(dl.x), e1 = __expf(dl.y);
        float s0 = e0, s1 = e1;
        #pragma unroll
        for (int sh = 16; sh > 0; sh >>= 1) {
            s0 += __shfl_xor_sync(0xffffffffu, s0, sh);
            s1 += __shfl_xor_sync(0xffffffffu, s1, sh);
        }
        u64t cp = pack2(__fdividef(e0, s0), __fdividef(e1, s1));

        #pragma unroll
        for (int k = 0; k < 16; k++) sacc[k] = fma2_(cp, V[k], sacc[k]);
    }

    float4* gp = (float4*)(g_part + (((size_t)c * NB + b) * NO + o) * 16);
    #pragma unroll
    for (int x = 0; x < 4; x++) {
        float2 a0 = unpack2(sacc[x * 4 + 0]);
        float2 a1 = unpack2(sacc[x * 4 + 1]);
        float2 a2 = unpack2(sacc[x * 4 + 2]);
        float2 a3 = unpack2(sacc[x * 4 + 3]);
        gp[x] = make_float4(a0.x + a0.y, a1.x + a1.y, a2.x + a2.y, a3.x + a3.y);
    }
}

__global__ __launch_bounds__(128, 4) void pass23_kernel()
{
    __shared__ u64t Ps[4][CP * 16];   // 8 KB
    __shared__ u64t Vd[4][16 * 32];   // 16 KB, [warp][k][o]
    int lane = threadIdx.x & 31, warp = threadIdx.x >> 5;
    pass23_body(blockIdx.x, blockIdx.y * 4 + warp, lane, Ps[warp], Vd[warp]);
}

// ---------------------------------------------------------------------------
// rs: single-level reduce over all 128 slabs + squash. 16384 threads,
// 128 blocks x 128 thr (SM spread); unroll 16 -> MLP 16 hides L2 latency.
// PHASE 0: v0 -> g_v, g_vsum.  PHASE 1: g_v = v0 + v1.  PHASE 2: write output.
// ---------------------------------------------------------------------------
template<int PHASE>
__global__ __launch_bounds__(128) void rs_kernel(float* __restrict__ out)
{
    int t = blockIdx.x * 128 + threadIdx.x;     // t = b*512 + o*16 + k
    float s = 0.f;
    const float* p = g_part + t;
    #pragma unroll 16
    for (int q = 0; q < NCHUNK; q++) s += __ldg(p + (size_t)q * PSLAB);
    if (PHASE == 0) s *= (1.0f / 32.0f);        // uniform coupling on iter 0

    float n2 = s * s;
    #pragma unroll
    for (int sh = 1; sh < 16; sh <<= 1)
        n2 += __shfl_xor_sync(0xffffffffu, n2, sh);   // sum over 16 pose elems

    float n = sqrtf(n2 + 1e-12f);
    float f = n2 / ((1.0f + n2) * n);
    float v = s * f;

    if (PHASE == 0)      { g_v[t] = v; g_vsum[t] = v; }
    else if (PHASE == 1) { g_v[t] = g_vsum[t] + v; }
    else {
        out[t] = v;                                     // capsule_poses [B,O,4,4]
        if ((t & 15) == 0)
            out[EL + (t >> 4)] = sqrtf(n2 * f * f + 1e-12f);  // activations
    }
}

extern "C" void kernel_launch(void* const* d_in, const int* in_sizes, int n_in,
                              void* d_out, int out_size)
{
    const float* poses = (const float*)d_in[0];
    // d_in[1] = input_activations — unused by the reference math
    const float* w     = (const float*)d_in[2];
    float* out = (float*)d_out;

    dim3 g1(NCHUNK, 4);    // pass1: 4 warps x 2 batches per block
    dim3 g23(NCHUNK, 8);   // pass23: 4 warps x 1 batch per block

    prep_kernel<<<8192, 256>>>(poses, w);       // launch 0

    pass1_kernel<<<g1, 128>>>();                // launch 1
    rs_kernel<0><<<EL / 128, 128>>>(nullptr);   // launch 2

    pass23_kernel<<<g23, 128>>>();              // launch 3  <- ncu capture slot
    rs_kernel<1><<<EL / 128, 128>>>(nullptr);   // launch 4

    pass23_kernel<<<g23, 128>>>();              // launch 5
    rs_kernel<2><<<EL / 128, 128>>>(out);       // launch 6
}